// round 11
// baseline (speedup 1.0000x reference)
#include <cuda_runtime.h>

#define NADDR 150000
#define NTX   200000
#define INDIM 64
#define HID   32
#define HEADS 4
#define EAT   1000000
#define ETA   1000000
#define EAA   500000

// block partitions
#define NB_A   18750            // NADDR/8 (exact)  -- lin_alpha
#define NB_T   25000            // NTX/8   (exact)
#define NB2_A  9375             // NADDR/16 (exact) -- agg (2 nodes/warp)
#define NB2_T  12500            // NTX/16   (exact)
#define SB0    196              // ceil(NTX/1024)
#define SB1    147              // ceil(NADDR/1024)
#define SB2    147

// ---------------- scratch (static device globals) -----------------------------------
__device__ float g_hA[NADDR*HID];
__device__ float g_hT[NTX*HID];
__device__ float g_accT[NTX*HID];
__device__ float g_accA1[NADDR*HID];
__device__ float g_accA2[NADDR*HID];
__device__ float g_as0[NADDR*HEADS];
__device__ float g_ad1[NADDR*HEADS];
__device__ float g_as2[NADDR*HEADS];
__device__ float g_ad2[NADDR*HEADS];
__device__ float g_tad0[NTX*HEADS];
__device__ float g_tas1[NTX*HEADS];
__device__ float g_tacc[2*64];         // double-buffered semantic accumulators (parity = layer&1)

__device__ int g_offsT[NTX + 1];
__device__ int g_offsA1[NADDR + 1];
__device__ int g_offsA2[NADDR + 1];
__device__ int g_csr0[EAT];
__device__ int g_csr1[ETA];
__device__ int g_csr2[EAA];
__device__ int g_cnt0[NTX];            // zero-initialized; scan1 re-zeroes after read
__device__ int g_cnt1[NADDR];
__device__ int g_cnt2[NADDR];
__device__ int g_cur0[NTX];
__device__ int g_cur1[NADDR];
__device__ int g_cur2[NADDR];
__device__ int g_bs0[256];
__device__ int g_bs1[256];
__device__ int g_bs2[256];

__device__ __forceinline__ float fast_tanh(float x) {
    return 1.f - __fdividef(2.f, __expf(2.f * x) + 1.f);
}

// ---------------- CSR build (4 launches total) ---------------------------------------
__global__ void csr_count_kernel(const int* __restrict__ d0, const int* __restrict__ d1,
                                 const int* __restrict__ d2) {
    int e = blockIdx.x * blockDim.x + threadIdx.x;
    if (e < EAT) atomicAdd(&g_cnt0[d0[e]], 1);
    if (e < ETA) atomicAdd(&g_cnt1[d1[e]], 1);
    if (e < EAA) atomicAdd(&g_cnt2[d2[e]], 1);
}
// per-1024-chunk exclusive scan; zeroes cnt after reading (ready for next invocation)
__global__ void csr_scan1_kernel() {
    __shared__ int ts[256];
    int b = blockIdx.x;
    int* cnt; int* offs; int* bs; int N; int lb;
    if (b < SB0)            { cnt = g_cnt0; offs = g_offsT;  bs = g_bs0; N = NTX;   lb = b; }
    else if (b < SB0 + SB1) { cnt = g_cnt1; offs = g_offsA1; bs = g_bs1; N = NADDR; lb = b - SB0; }
    else                    { cnt = g_cnt2; offs = g_offsA2; bs = g_bs2; N = NADDR; lb = b - SB0 - SB1; }
    int tid = threadIdx.x;
    int base = lb * 1024;
    int v[4]; int sum = 0;
    #pragma unroll
    for (int j = 0; j < 4; j++) {
        int idx = base + tid * 4 + j;
        v[j] = (idx < N) ? cnt[idx] : 0;
        if (idx < N) cnt[idx] = 0;          // reset for next graph replay
        sum += v[j];
    }
    ts[tid] = sum;
    __syncthreads();
    for (int off = 1; off < 256; off <<= 1) {
        int t = (tid >= off) ? ts[tid - off] : 0;
        __syncthreads();
        ts[tid] += t;
        __syncthreads();
    }
    int run = ts[tid] - sum;
    #pragma unroll
    for (int j = 0; j < 4; j++) {
        int idx = base + tid * 4 + j;
        if (idx < N) offs[idx] = run;
        run += v[j];
    }
    if (tid == 255) bs[lb] = ts[255];
}
// adds block-sum prefixes (computed locally from smem) and initializes cursors
__global__ void csr_scan3_kernel() {
    __shared__ int sb0[SB0], sb1[SB1], sb2[SB2];
    int tid = threadIdx.x;
    for (int i = tid; i < SB0; i += 256) sb0[i] = g_bs0[i];
    for (int i = tid; i < SB1; i += 256) sb1[i] = g_bs1[i];
    for (int i = tid; i < SB2; i += 256) sb2[i] = g_bs2[i];
    __syncthreads();
    int i = blockIdx.x * 256 + tid;
    if (i < NTX) {
        int lb = i >> 10, pre = 0;
        for (int k = 0; k < lb; k++) pre += sb0[k];
        int o = g_offsT[i] + pre;
        g_offsT[i] = o; g_cur0[i] = o;
    }
    if (i < NADDR) {
        int lb = i >> 10, p1 = 0, p2 = 0;
        for (int k = 0; k < lb; k++) { p1 += sb1[k]; p2 += sb2[k]; }
        int o = g_offsA1[i] + p1;
        g_offsA1[i] = o; g_cur1[i] = o;
        o = g_offsA2[i] + p2;
        g_offsA2[i] = o; g_cur2[i] = o;
    }
    if (i == 0) { g_offsT[NTX] = EAT; g_offsA1[NADDR] = ETA; g_offsA2[NADDR] = EAA; }
}
__global__ void csr_scatter_kernel(const int* __restrict__ s0, const int* __restrict__ d0,
                                   const int* __restrict__ s1, const int* __restrict__ d1,
                                   const int* __restrict__ s2, const int* __restrict__ d2) {
    int e = blockIdx.x * blockDim.x + threadIdx.x;
    if (e < EAT) { int p = atomicAdd(&g_cur0[d0[e]], 1); g_csr0[p] = s0[e]; }
    if (e < ETA) { int p = atomicAdd(&g_cur1[d1[e]], 1); g_csr1[p] = s1[e]; }
    if (e < EAA) { int p = atomicAdd(&g_cur2[d2[e]], 1); g_csr2[p] = s2[e]; }
}

// ---------------- fused: [semantic combine] + linear projection + attention dots -----
// warp = node; lane j = output feature. For l>0 the addr input row is formed on the
// fly as relu(attn0*accA1 + attn1*accA2); attn weights recomputed per block from tacc.
__global__ void __launch_bounds__(256) lin_alpha_kernel(
        int l, const float* __restrict__ xa_ext, const float* __restrict__ xt_ext,
        const float* __restrict__ Wa, const float* __restrict__ ba,
        const float* __restrict__ Wt, const float* __restrict__ bt,
        const float* __restrict__ As, const float* __restrict__ Ad,
        const float* __restrict__ q_prev, int IN) {
    __shared__ float Ws[INDIM*HID];
    __shared__ float Att[4*HID];
    __shared__ float sAttn[2];
    bool is_addr = blockIdx.x < NB_A;
    int tid = threadIdx.x;

    // zero this layer's semantic accumulator buffer (parity l&1); consumers of the
    // previous layer read parity (l-1)&1 — different buffer, no race.
    if (blockIdx.x == 0 && tid < 64) g_tacc[(l & 1) * 64 + tid] = 0.f;

    const float* W = is_addr ? Wa : Wt;
    for (int i = tid; i < IN*HID; i += 256) Ws[i] = W[i];
    if (is_addr) {
        if (tid < HID)        Att[tid] = As[tid];                    // as0
        else if (tid < 2*HID) Att[tid] = Ad[HID + (tid-HID)];        // ad1
        else if (tid < 3*HID) Att[tid] = As[2*HID + (tid-2*HID)];    // as2
        else if (tid < 4*HID) Att[tid] = Ad[2*HID + (tid-3*HID)];    // ad2
    } else {
        if (tid < HID)        Att[tid] = Ad[tid];                    // tad0
        else if (tid < 2*HID) Att[tid] = As[HID + (tid-HID)];        // tas1
    }
    if (l > 0 && tid < 32) {       // semantic attention weights of previous layer
        int prev = (l - 1) & 1;
        float qv = q_prev[tid];
        float p0 = g_tacc[prev*64 + tid] * qv;
        float p1 = g_tacc[prev*64 + 32 + tid] * qv;
        #pragma unroll
        for (int o = 16; o >= 1; o >>= 1) {
            p0 += __shfl_xor_sync(0xffffffffu, p0, o);
            p1 += __shfl_xor_sync(0xffffffffu, p1, o);
        }
        if (tid == 0) {
            float s0 = p0 * (1.f / NADDR), s1 = p1 * (1.f / NADDR);
            float m = fmaxf(s0, s1);
            float e0 = __expf(s0 - m), e1 = __expf(s1 - m);
            sAttn[0] = e0 / (e0 + e1);
            sAttn[1] = e1 / (e0 + e1);
        }
    }
    __syncthreads();

    int slot = tid >> 5, j = tid & 31;
    int n = (is_addr ? blockIdx.x : blockIdx.x - NB_A) * 8 + slot;

    float acc = is_addr ? ba[j] : bt[j];
    if (l == 0) {
        const float* xr = (is_addr ? xa_ext : xt_ext) + (long)n * IN;
        #pragma unroll 8
        for (int k = 0; k < IN; k++) acc = fmaf(xr[k], Ws[k*HID + j], acc);
    } else {
        // lane owns one input feature; distribute via shuffle
        float c;
        if (is_addr) {
            float a1 = g_accA1[(long)n*HID + j];
            float a2 = g_accA2[(long)n*HID + j];
            c = fmaxf(sAttn[0]*a1 + sAttn[1]*a2, 0.f);
        } else {
            c = g_accT[(long)n*HID + j];
        }
        #pragma unroll
        for (int k = 0; k < HID; k++)
            acc = fmaf(__shfl_sync(0xffffffffu, c, k), Ws[k*HID + j], acc);
    }

    float* y = is_addr ? g_hA : g_hT;
    y[(long)n*HID + j] = acc;

    int grp = j >> 3;
    unsigned m = 0xffffffffu;
    if (is_addr) {
        float p0 = acc * Att[j],       p1 = acc * Att[HID + j];
        float p2 = acc * Att[2*HID+j], p3 = acc * Att[3*HID + j];
        #pragma unroll
        for (int o = 4; o >= 1; o >>= 1) {
            p0 += __shfl_xor_sync(m, p0, o);
            p1 += __shfl_xor_sync(m, p1, o);
            p2 += __shfl_xor_sync(m, p2, o);
            p3 += __shfl_xor_sync(m, p3, o);
        }
        if ((j & 7) == 0) {
            g_as0[n*4 + grp] = p0; g_ad1[n*4 + grp] = p1;
            g_as2[n*4 + grp] = p2; g_ad2[n*4 + grp] = p3;
        }
    } else {
        float p0 = acc * Att[j], p1 = acc * Att[HID + j];
        #pragma unroll
        for (int o = 4; o >= 1; o >>= 1) {
            p0 += __shfl_xor_sync(m, p0, o);
            p1 += __shfl_xor_sync(m, p1, o);
        }
        if ((j & 7) == 0) {
            g_tad0[n*4 + grp] = p0; g_tas1[n*4 + grp] = p1;
        }
    }
}

// ---------------- gather aggregation: 2 nodes per warp (half-warp per node) ----------
// Lane 0-15 = node A, 16-31 = node B. Each lane owns 2 features via one float2 load,
// head = (lane&15)>>2, so exactly one alpha value per lane. Two independent gather
// chains per warp -> 2x memory-level parallelism vs warp-per-node.
// base shifts the relation ranges so layer 2 can skip relation 0 (o_tx unused).
__global__ void __launch_bounds__(256) agg_kernel(int base) {
    int b = blockIdx.x + base;
    const int *offs, *csr;
    const float *asv, *adv, *hs;
    float* out;
    int nb;
    if (b < NB2_T) {
        offs = g_offsT;  csr = g_csr0; asv = g_as0;  adv = g_tad0;
        hs = g_hA; out = g_accT;  nb = b;
    } else if (b < NB2_T + NB2_A) {
        offs = g_offsA1; csr = g_csr1; asv = g_tas1; adv = g_ad1;
        hs = g_hT; out = g_accA1; nb = b - NB2_T;
    } else {
        offs = g_offsA2; csr = g_csr2; asv = g_as2;  adv = g_ad2;
        hs = g_hA; out = g_accA2; nb = b - NB2_T - NB2_A;
    }
    int lane = threadIdx.x & 31;
    int half = lane >> 4;                       // node within pair
    int hl = lane & 15;                         // lane within node-half
    int n = nb * 16 + (threadIdx.x >> 5) * 2 + half;
    int h = hl >> 2;                            // head of this lane's feature pair
    const float2* hp = (const float2*)hs;

    float ad = __ldg(adv + n*4 + h);
    int beg = __ldg(offs + n), end = __ldg(offs + n + 1);
    float ax = 0.f, ay = 0.f, den = 0.f;
    int k = beg;
    for (; k + 4 <= end; k += 4) {
        int s0 = __ldg(csr + k),     s1 = __ldg(csr + k + 1);
        int s2 = __ldg(csr + k + 2), s3 = __ldg(csr + k + 3);
        float a0 = __ldg(asv + s0*4 + h), a1 = __ldg(asv + s1*4 + h);
        float a2 = __ldg(asv + s2*4 + h), a3 = __ldg(asv + s3*4 + h);
        float2 r0 = hp[s0*16 + hl];
        float2 r1 = hp[s1*16 + hl];
        float2 r2 = hp[s2*16 + hl];
        float2 r3 = hp[s3*16 + hl];
        a0 += ad; a1 += ad; a2 += ad; a3 += ad;
        a0 = fmaxf(a0, 0.2f*a0); a1 = fmaxf(a1, 0.2f*a1);   // leaky_relu (slope<1)
        a2 = fmaxf(a2, 0.2f*a2); a3 = fmaxf(a3, 0.2f*a3);
        float e0 = __expf(a0), e1 = __expf(a1), e2 = __expf(a2), e3 = __expf(a3);
        den += (e0 + e1) + (e2 + e3);
        ax = fmaf(e0, r0.x, ax); ay = fmaf(e0, r0.y, ay);
        ax = fmaf(e1, r1.x, ax); ay = fmaf(e1, r1.y, ay);
        ax = fmaf(e2, r2.x, ax); ay = fmaf(e2, r2.y, ay);
        ax = fmaf(e3, r3.x, ax); ay = fmaf(e3, r3.y, ay);
    }
    for (; k < end; k++) {
        int s = __ldg(csr + k);
        float l = __ldg(asv + s*4 + h) + ad;
        l = fmaxf(l, 0.2f*l);
        float ev = __expf(l);
        float2 r = hp[s*16 + hl];
        den += ev;
        ax = fmaf(ev, r.x, ax); ay = fmaf(ev, r.y, ay);
    }
    float inv = 1.f / (den + 1e-16f);
    float2 v = make_float2(fmaxf(ax * inv, 0.f), fmaxf(ay * inv, 0.f));
    ((float2*)out)[n*16 + hl] = v;
}

// ---------------- semantic attention mean (both relations, into parity buffer) ------
__global__ void __launch_bounds__(256) sem_kernel(const float* __restrict__ kW,
                                                  const float* __restrict__ kb, int par) {
    __shared__ float Ws[HID*HID];
    __shared__ float red1[256], red2[256];
    int tid = threadIdx.x;
    for (int i = tid; i < HID*HID; i += 256) Ws[i] = kW[i];
    __syncthreads();
    int j = tid & 31, slot = tid >> 5;
    float bj = kb[j];
    float a1 = 0.f, a2 = 0.f;
    int n0 = blockIdx.x * 256 + slot;
    for (int it = 0; it < 32; it++) {
        int n = n0 + it*8;
        if (n < NADDR) {
            const float* r1 = g_accA1 + (long)n*HID;
            const float* r2 = g_accA2 + (long)n*HID;
            float d1 = bj, d2 = bj;
            #pragma unroll
            for (int k = 0; k < HID; k++) {
                float w = Ws[k*HID + j];
                d1 = fmaf(r1[k], w, d1);
                d2 = fmaf(r2[k], w, d2);
            }
            a1 += fast_tanh(d1);
            a2 += fast_tanh(d2);
        }
    }
    red1[tid] = a1; red2[tid] = a2;
    __syncthreads();
    if (slot == 0) {
        float s1 = 0.f, s2 = 0.f;
        #pragma unroll
        for (int ss = 0; ss < 8; ss++) { s1 += red1[ss*32 + j]; s2 += red2[ss*32 + j]; }
        atomicAdd(&g_tacc[par*64 + j], s1);
        atomicAdd(&g_tacc[par*64 + 32 + j], s2);
    }
}

// ---------------- final: inline attn + semantic combine + linear ---------------------
__global__ void final_kernel(const float* __restrict__ q2, const float* __restrict__ W,
                             const float* __restrict__ b, float* __restrict__ out) {
    __shared__ float sAttn[2];
    int tid = threadIdx.x;
    if (tid < 32) {                           // layer 2 parity = 0
        float qv = q2[tid];
        float p0 = g_tacc[tid] * qv;
        float p1 = g_tacc[32 + tid] * qv;
        #pragma unroll
        for (int o = 16; o >= 1; o >>= 1) {
            p0 += __shfl_xor_sync(0xffffffffu, p0, o);
            p1 += __shfl_xor_sync(0xffffffffu, p1, o);
        }
        if (tid == 0) {
            float s0 = p0 * (1.f / NADDR), s1 = p1 * (1.f / NADDR);
            float m = fmaxf(s0, s1);
            float e0 = __expf(s0 - m), e1 = __expf(s1 - m);
            sAttn[0] = e0 / (e0 + e1);
            sAttn[1] = e1 / (e0 + e1);
        }
    }
    __syncthreads();
    int n = blockIdx.x * blockDim.x + tid;
    if (n >= NADDR) return;
    float at0 = sAttn[0], at1 = sAttn[1];
    float a0 = b[0], a1 = b[1];
    const float* r1 = g_accA1 + (long)n*HID;
    const float* r2 = g_accA2 + (long)n*HID;
    #pragma unroll
    for (int k = 0; k < HID; k++) {
        float v = fmaxf(at0*r1[k] + at1*r2[k], 0.f);
        a0 = fmaf(v, W[k*2],     a0);
        a1 = fmaf(v, W[k*2 + 1], a1);
    }
    out[n*2] = a0;
    out[n*2 + 1] = a1;
}

// ---------------- host orchestration -------------------------------------------------
extern "C" void kernel_launch(void* const* d_in, const int* in_sizes, int n_in,
                              void* d_out, int out_size) {
    const float* x_addr  = (const float*)d_in[0];
    const float* x_tx    = (const float*)d_in[1];
    const int*   eat_s   = (const int*)d_in[2];
    const int*   eat_d   = (const int*)d_in[3];
    const int*   eta_s   = (const int*)d_in[4];
    const int*   eta_d   = (const int*)d_in[5];
    const int*   eaa_s   = (const int*)d_in[6];
    const int*   eaa_d   = (const int*)d_in[7];
    const float* pW1     = (const float*)d_in[8];
    const float* pb1     = (const float*)d_in[9];
    const float* pW23    = (const float*)d_in[10];
    const float* pb23    = (const float*)d_in[11];
    const float* att_src = (const float*)d_in[12];
    const float* att_dst = (const float*)d_in[13];
    const float* kW      = (const float*)d_in[14];
    const float* kb      = (const float*)d_in[15];
    const float* q       = (const float*)d_in[16];
    const float* linW    = (const float*)d_in[17];
    const float* linb    = (const float*)d_in[18];

    // CSR build (4 launches; counters re-zero themselves each invocation)
    csr_count_kernel<<<(EAT + 255)/256, 256>>>(eat_d, eta_d, eaa_d);
    csr_scan1_kernel<<<SB0 + SB1 + SB2, 256>>>();
    csr_scan3_kernel<<<(NTX + 255)/256, 256>>>();
    csr_scatter_kernel<<<(EAT + 255)/256, 256>>>(eat_s, eat_d, eta_s, eta_d, eaa_s, eaa_d);

    for (int l = 0; l < 3; l++) {
        const float *Wa, *ba, *Wt, *bt;
        int IN;
        if (l == 0) {
            Wa = pW1;               ba = pb1;
            Wt = pW1 + INDIM*HID;   bt = pb1 + HID;
            IN = INDIM;
        } else {
            Wa = pW23 + ((l-1)*2 + 0)*HID*HID;  ba = pb23 + ((l-1)*2 + 0)*HID;
            Wt = pW23 + ((l-1)*2 + 1)*HID*HID;  bt = pb23 + ((l-1)*2 + 1)*HID;
            IN = HID;
        }
        const float* As = att_src + (l*3) * HEADS * 8;
        const float* Ad = att_dst + (l*3) * HEADS * 8;
        const float* qp = (l == 0) ? q : q + (l-1)*HID;

        lin_alpha_kernel<<<NB_A + NB_T, 256>>>(l, x_addr, x_tx, Wa, ba, Wt, bt,
                                               As, Ad, qp, IN);
        if (l < 2) {
            agg_kernel<<<NB2_T + 2*NB2_A, 256>>>(0);          // all 3 relations
        } else {
            agg_kernel<<<2*NB2_A, 256>>>(NB2_T);              // skip rel0: o_tx unused
        }
        sem_kernel<<<(NADDR + 255)/256, 256>>>(kW + l*HID*HID, kb + l*HID, l & 1);
    }
    final_kernel<<<(NADDR + 255)/256, 256>>>(q + 2*HID, linW, linb, (float*)d_out);
}

// round 17
// speedup vs baseline: 1.3977x; 1.3977x over previous
#include <cuda_runtime.h>

#define NADDR 150000
#define NTX   200000
#define INDIM 64
#define HID   32
#define HEADS 4
#define EAT   1000000
#define ETA   1000000
#define EAA   500000

// block partitions
#define NB_A   18750            // NADDR/8 (exact)
#define NB_T   25000            // NTX/8   (exact)
#define SB0    196              // ceil(NTX/1024)
#define SB1    147              // ceil(NADDR/1024)
#define SB2    147

// ---------------- scratch (static device globals) -----------------------------------
__device__ float g_hA[NADDR*HID];
__device__ float g_hT[NTX*HID];
__device__ float g_accT[NTX*HID];
__device__ float g_accA1[NADDR*HID];
__device__ float g_accA2[NADDR*HID];
__device__ float g_as0[NADDR*HEADS];
__device__ float g_ad1[NADDR*HEADS];
__device__ float g_as2[NADDR*HEADS];
__device__ float g_ad2[NADDR*HEADS];
__device__ float g_tad0[NTX*HEADS];
__device__ float g_tas1[NTX*HEADS];
__device__ float g_tacc[2*64];         // double-buffered semantic accumulators (parity = layer&1)

__device__ int g_offsT[NTX + 1];
__device__ int g_offsA1[NADDR + 1];
__device__ int g_offsA2[NADDR + 1];
__device__ int g_csr0[EAT];
__device__ int g_csr1[ETA];
__device__ int g_csr2[EAA];
__device__ int g_cnt0[NTX];            // zero-initialized; scan1 re-zeroes after read
__device__ int g_cnt1[NADDR];
__device__ int g_cnt2[NADDR];
__device__ int g_cur0[NTX];
__device__ int g_cur1[NADDR];
__device__ int g_cur2[NADDR];
__device__ int g_bs0[256];
__device__ int g_bs1[256];
__device__ int g_bs2[256];

__device__ __forceinline__ float fast_tanh(float x) {
    return 1.f - __fdividef(2.f, __expf(2.f * x) + 1.f);
}

// ---------------- CSR build (4 launches total) ---------------------------------------
__global__ void csr_count_kernel(const int* __restrict__ d0, const int* __restrict__ d1,
                                 const int* __restrict__ d2) {
    int e = blockIdx.x * blockDim.x + threadIdx.x;
    if (e < EAT) atomicAdd(&g_cnt0[d0[e]], 1);
    if (e < ETA) atomicAdd(&g_cnt1[d1[e]], 1);
    if (e < EAA) atomicAdd(&g_cnt2[d2[e]], 1);
}
// per-1024-chunk exclusive scan; zeroes cnt after reading (ready for next invocation)
__global__ void csr_scan1_kernel() {
    __shared__ int ts[256];
    int b = blockIdx.x;
    int* cnt; int* offs; int* bs; int N; int lb;
    if (b < SB0)            { cnt = g_cnt0; offs = g_offsT;  bs = g_bs0; N = NTX;   lb = b; }
    else if (b < SB0 + SB1) { cnt = g_cnt1; offs = g_offsA1; bs = g_bs1; N = NADDR; lb = b - SB0; }
    else                    { cnt = g_cnt2; offs = g_offsA2; bs = g_bs2; N = NADDR; lb = b - SB0 - SB1; }
    int tid = threadIdx.x;
    int base = lb * 1024;
    int v[4]; int sum = 0;
    #pragma unroll
    for (int j = 0; j < 4; j++) {
        int idx = base + tid * 4 + j;
        v[j] = (idx < N) ? cnt[idx] : 0;
        if (idx < N) cnt[idx] = 0;          // reset for next graph replay
        sum += v[j];
    }
    ts[tid] = sum;
    __syncthreads();
    for (int off = 1; off < 256; off <<= 1) {
        int t = (tid >= off) ? ts[tid - off] : 0;
        __syncthreads();
        ts[tid] += t;
        __syncthreads();
    }
    int run = ts[tid] - sum;
    #pragma unroll
    for (int j = 0; j < 4; j++) {
        int idx = base + tid * 4 + j;
        if (idx < N) offs[idx] = run;
        run += v[j];
    }
    if (tid == 255) bs[lb] = ts[255];
}
// adds block-sum prefixes (computed locally from smem) and initializes cursors
__global__ void csr_scan3_kernel() {
    __shared__ int sb0[SB0], sb1[SB1], sb2[SB2];
    int tid = threadIdx.x;
    for (int i = tid; i < SB0; i += 256) sb0[i] = g_bs0[i];
    for (int i = tid; i < SB1; i += 256) sb1[i] = g_bs1[i];
    for (int i = tid; i < SB2; i += 256) sb2[i] = g_bs2[i];
    __syncthreads();
    int i = blockIdx.x * 256 + tid;
    if (i < NTX) {
        int lb = i >> 10, pre = 0;
        for (int k = 0; k < lb; k++) pre += sb0[k];
        int o = g_offsT[i] + pre;
        g_offsT[i] = o; g_cur0[i] = o;
    }
    if (i < NADDR) {
        int lb = i >> 10, p1 = 0, p2 = 0;
        for (int k = 0; k < lb; k++) { p1 += sb1[k]; p2 += sb2[k]; }
        int o = g_offsA1[i] + p1;
        g_offsA1[i] = o; g_cur1[i] = o;
        o = g_offsA2[i] + p2;
        g_offsA2[i] = o; g_cur2[i] = o;
    }
    if (i == 0) { g_offsT[NTX] = EAT; g_offsA1[NADDR] = ETA; g_offsA2[NADDR] = EAA; }
}
__global__ void csr_scatter_kernel(const int* __restrict__ s0, const int* __restrict__ d0,
                                   const int* __restrict__ s1, const int* __restrict__ d1,
                                   const int* __restrict__ s2, const int* __restrict__ d2) {
    int e = blockIdx.x * blockDim.x + threadIdx.x;
    if (e < EAT) { int p = atomicAdd(&g_cur0[d0[e]], 1); g_csr0[p] = s0[e]; }
    if (e < ETA) { int p = atomicAdd(&g_cur1[d1[e]], 1); g_csr1[p] = s1[e]; }
    if (e < EAA) { int p = atomicAdd(&g_cur2[d2[e]], 1); g_csr2[p] = s2[e]; }
}

// ---------------- fused: [semantic combine] + linear projection + attention dots -----
// warp = node; lane j = output feature. For l>0 the addr input row is formed on the
// fly as relu(attn0*accA1 + attn1*accA2); attn weights recomputed per block from tacc.
__global__ void __launch_bounds__(256) lin_alpha_kernel(
        int l, const float* __restrict__ xa_ext, const float* __restrict__ xt_ext,
        const float* __restrict__ Wa, const float* __restrict__ ba,
        const float* __restrict__ Wt, const float* __restrict__ bt,
        const float* __restrict__ As, const float* __restrict__ Ad,
        const float* __restrict__ q_prev, int IN) {
    __shared__ float Ws[INDIM*HID];
    __shared__ float Att[4*HID];
    __shared__ float sAttn[2];
    bool is_addr = blockIdx.x < NB_A;
    int tid = threadIdx.x;

    // zero this layer's semantic accumulator buffer (parity l&1); consumers of the
    // previous layer read parity (l-1)&1 — different buffer, no race.
    if (blockIdx.x == 0 && tid < 64) g_tacc[(l & 1) * 64 + tid] = 0.f;

    const float* W = is_addr ? Wa : Wt;
    for (int i = tid; i < IN*HID; i += 256) Ws[i] = W[i];
    if (is_addr) {
        if (tid < HID)        Att[tid] = As[tid];                    // as0
        else if (tid < 2*HID) Att[tid] = Ad[HID + (tid-HID)];        // ad1
        else if (tid < 3*HID) Att[tid] = As[2*HID + (tid-2*HID)];    // as2
        else if (tid < 4*HID) Att[tid] = Ad[2*HID + (tid-3*HID)];    // ad2
    } else {
        if (tid < HID)        Att[tid] = Ad[tid];                    // tad0
        else if (tid < 2*HID) Att[tid] = As[HID + (tid-HID)];        // tas1
    }
    if (l > 0 && tid < 32) {       // semantic attention weights of previous layer
        int prev = (l - 1) & 1;
        float qv = q_prev[tid];
        float p0 = g_tacc[prev*64 + tid] * qv;
        float p1 = g_tacc[prev*64 + 32 + tid] * qv;
        #pragma unroll
        for (int o = 16; o >= 1; o >>= 1) {
            p0 += __shfl_xor_sync(0xffffffffu, p0, o);
            p1 += __shfl_xor_sync(0xffffffffu, p1, o);
        }
        if (tid == 0) {
            float s0 = p0 * (1.f / NADDR), s1 = p1 * (1.f / NADDR);
            float m = fmaxf(s0, s1);
            float e0 = __expf(s0 - m), e1 = __expf(s1 - m);
            sAttn[0] = e0 / (e0 + e1);
            sAttn[1] = e1 / (e0 + e1);
        }
    }
    __syncthreads();

    int slot = tid >> 5, j = tid & 31;
    int n = (is_addr ? blockIdx.x : blockIdx.x - NB_A) * 8 + slot;

    float acc = is_addr ? ba[j] : bt[j];
    if (l == 0) {
        const float* xr = (is_addr ? xa_ext : xt_ext) + (long)n * IN;
        #pragma unroll 8
        for (int k = 0; k < IN; k++) acc = fmaf(xr[k], Ws[k*HID + j], acc);
    } else {
        // lane owns one input feature; distribute via shuffle
        float c;
        if (is_addr) {
            float a1 = g_accA1[(long)n*HID + j];
            float a2 = g_accA2[(long)n*HID + j];
            c = fmaxf(sAttn[0]*a1 + sAttn[1]*a2, 0.f);
        } else {
            c = g_accT[(long)n*HID + j];
        }
        #pragma unroll
        for (int k = 0; k < HID; k++)
            acc = fmaf(__shfl_sync(0xffffffffu, c, k), Ws[k*HID + j], acc);
    }

    float* y = is_addr ? g_hA : g_hT;
    y[(long)n*HID + j] = acc;

    int grp = j >> 3;
    unsigned m = 0xffffffffu;
    if (is_addr) {
        float p0 = acc * Att[j],       p1 = acc * Att[HID + j];
        float p2 = acc * Att[2*HID+j], p3 = acc * Att[3*HID + j];
        #pragma unroll
        for (int o = 4; o >= 1; o >>= 1) {
            p0 += __shfl_xor_sync(m, p0, o);
            p1 += __shfl_xor_sync(m, p1, o);
            p2 += __shfl_xor_sync(m, p2, o);
            p3 += __shfl_xor_sync(m, p3, o);
        }
        if ((j & 7) == 0) {
            g_as0[n*4 + grp] = p0; g_ad1[n*4 + grp] = p1;
            g_as2[n*4 + grp] = p2; g_ad2[n*4 + grp] = p3;
        }
    } else {
        float p0 = acc * Att[j], p1 = acc * Att[HID + j];
        #pragma unroll
        for (int o = 4; o >= 1; o >>= 1) {
            p0 += __shfl_xor_sync(m, p0, o);
            p1 += __shfl_xor_sync(m, p1, o);
        }
        if ((j & 7) == 0) {
            g_tad0[n*4 + grp] = p0; g_tas1[n*4 + grp] = p1;
        }
    }
}

// ---------------- gather aggregation: warp-per-node, unroll-4 (R8 layout) ------------
// base shifts the relation block ranges so layer 2 can skip relation 0 (o_tx unused).
__global__ void __launch_bounds__(256) agg_kernel(int base) {
    int b = blockIdx.x + base;
    const int *offs, *csr;
    const float *asv, *adv, *hs;
    float* out;
    int nb;
    if (b < NB_T) {
        offs = g_offsT;  csr = g_csr0; asv = g_as0;  adv = g_tad0;
        hs = g_hA; out = g_accT;  nb = b;
    } else if (b < NB_T + NB_A) {
        offs = g_offsA1; csr = g_csr1; asv = g_tas1; adv = g_ad1;
        hs = g_hT; out = g_accA1; nb = b - NB_T;
    } else {
        offs = g_offsA2; csr = g_csr2; asv = g_as2;  adv = g_ad2;
        hs = g_hA; out = g_accA2; nb = b - NB_T - NB_A;
    }
    int n = nb * 8 + (threadIdx.x >> 5);
    int lane = threadIdx.x & 31;
    int h = lane >> 3;
    float ad = __ldg(adv + n*4 + h);
    int beg = __ldg(offs + n), end = __ldg(offs + n + 1);
    float acc = 0.f, den = 0.f;
    int k = beg;
    for (; k + 4 <= end; k += 4) {
        int s0 = __ldg(csr + k),     s1 = __ldg(csr + k + 1);
        int s2 = __ldg(csr + k + 2), s3 = __ldg(csr + k + 3);
        float a0 = __ldg(asv + s0*4 + h), a1 = __ldg(asv + s1*4 + h);
        float a2 = __ldg(asv + s2*4 + h), a3 = __ldg(asv + s3*4 + h);
        float r0 = __ldg(hs + ((long)s0 << 5) + lane);
        float r1 = __ldg(hs + ((long)s1 << 5) + lane);
        float r2 = __ldg(hs + ((long)s2 << 5) + lane);
        float r3 = __ldg(hs + ((long)s3 << 5) + lane);
        a0 += ad; a1 += ad; a2 += ad; a3 += ad;
        a0 = fmaxf(a0, 0.2f*a0); a1 = fmaxf(a1, 0.2f*a1);   // leaky_relu (slope<1)
        a2 = fmaxf(a2, 0.2f*a2); a3 = fmaxf(a3, 0.2f*a3);
        float e0 = __expf(a0), e1 = __expf(a1), e2 = __expf(a2), e3 = __expf(a3);
        den += (e0 + e1) + (e2 + e3);
        acc = fmaf(e0, r0, acc); acc = fmaf(e1, r1, acc);
        acc = fmaf(e2, r2, acc); acc = fmaf(e3, r3, acc);
    }
    for (; k < end; k++) {
        int s = __ldg(csr + k);
        float l = __ldg(asv + s*4 + h) + ad;
        l = fmaxf(l, 0.2f*l);
        float ev = __expf(l);
        den += ev;
        acc = fmaf(ev, __ldg(hs + ((long)s << 5) + lane), acc);
    }
    float v = acc / (den + 1e-16f);
    out[(long)n*HID + lane] = fmaxf(v, 0.f);
}

// ---------------- semantic attention mean (both relations, into parity buffer) ------
__global__ void __launch_bounds__(256) sem_kernel(const float* __restrict__ kW,
                                                  const float* __restrict__ kb, int par) {
    __shared__ float Ws[HID*HID];
    __shared__ float red1[256], red2[256];
    int tid = threadIdx.x;
    for (int i = tid; i < HID*HID; i += 256) Ws[i] = kW[i];
    __syncthreads();
    int j = tid & 31, slot = tid >> 5;
    float bj = kb[j];
    float a1 = 0.f, a2 = 0.f;
    int n0 = blockIdx.x * 256 + slot;
    for (int it = 0; it < 32; it++) {
        int n = n0 + it*8;
        if (n < NADDR) {
            const float* r1 = g_accA1 + (long)n*HID;
            const float* r2 = g_accA2 + (long)n*HID;
            float d1 = bj, d2 = bj;
            #pragma unroll
            for (int k = 0; k < HID; k++) {
                float w = Ws[k*HID + j];
                d1 = fmaf(r1[k], w, d1);
                d2 = fmaf(r2[k], w, d2);
            }
            a1 += fast_tanh(d1);
            a2 += fast_tanh(d2);
        }
    }
    red1[tid] = a1; red2[tid] = a2;
    __syncthreads();
    if (slot == 0) {
        float s1 = 0.f, s2 = 0.f;
        #pragma unroll
        for (int ss = 0; ss < 8; ss++) { s1 += red1[ss*32 + j]; s2 += red2[ss*32 + j]; }
        atomicAdd(&g_tacc[par*64 + j], s1);
        atomicAdd(&g_tacc[par*64 + 32 + j], s2);
    }
}

// ---------------- final: inline attn + semantic combine + linear ---------------------
__global__ void final_kernel(const float* __restrict__ q2, const float* __restrict__ W,
                             const float* __restrict__ b, float* __restrict__ out) {
    __shared__ float sAttn[2];
    int tid = threadIdx.x;
    if (tid < 32) {                           // layer 2 parity = 0
        float qv = q2[tid];
        float p0 = g_tacc[tid] * qv;
        float p1 = g_tacc[32 + tid] * qv;
        #pragma unroll
        for (int o = 16; o >= 1; o >>= 1) {
            p0 += __shfl_xor_sync(0xffffffffu, p0, o);
            p1 += __shfl_xor_sync(0xffffffffu, p1, o);
        }
        if (tid == 0) {
            float s0 = p0 * (1.f / NADDR), s1 = p1 * (1.f / NADDR);
            float m = fmaxf(s0, s1);
            float e0 = __expf(s0 - m), e1 = __expf(s1 - m);
            sAttn[0] = e0 / (e0 + e1);
            sAttn[1] = e1 / (e0 + e1);
        }
    }
    __syncthreads();
    int n = blockIdx.x * blockDim.x + tid;
    if (n >= NADDR) return;
    float at0 = sAttn[0], at1 = sAttn[1];
    float a0 = b[0], a1 = b[1];
    const float* r1 = g_accA1 + (long)n*HID;
    const float* r2 = g_accA2 + (long)n*HID;
    #pragma unroll
    for (int k = 0; k < HID; k++) {
        float v = fmaxf(at0*r1[k] + at1*r2[k], 0.f);
        a0 = fmaf(v, W[k*2],     a0);
        a1 = fmaf(v, W[k*2 + 1], a1);
    }
    out[n*2] = a0;
    out[n*2 + 1] = a1;
}

// ---------------- host orchestration -------------------------------------------------
extern "C" void kernel_launch(void* const* d_in, const int* in_sizes, int n_in,
                              void* d_out, int out_size) {
    const float* x_addr  = (const float*)d_in[0];
    const float* x_tx    = (const float*)d_in[1];
    const int*   eat_s   = (const int*)d_in[2];
    const int*   eat_d   = (const int*)d_in[3];
    const int*   eta_s   = (const int*)d_in[4];
    const int*   eta_d   = (const int*)d_in[5];
    const int*   eaa_s   = (const int*)d_in[6];
    const int*   eaa_d   = (const int*)d_in[7];
    const float* pW1     = (const float*)d_in[8];
    const float* pb1     = (const float*)d_in[9];
    const float* pW23    = (const float*)d_in[10];
    const float* pb23    = (const float*)d_in[11];
    const float* att_src = (const float*)d_in[12];
    const float* att_dst = (const float*)d_in[13];
    const float* kW      = (const float*)d_in[14];
    const float* kb      = (const float*)d_in[15];
    const float* q       = (const float*)d_in[16];
    const float* linW    = (const float*)d_in[17];
    const float* linb    = (const float*)d_in[18];

    // CSR build (4 launches; counters re-zero themselves each invocation)
    csr_count_kernel<<<(EAT + 255)/256, 256>>>(eat_d, eta_d, eaa_d);
    csr_scan1_kernel<<<SB0 + SB1 + SB2, 256>>>();
    csr_scan3_kernel<<<(NTX + 255)/256, 256>>>();
    csr_scatter_kernel<<<(EAT + 255)/256, 256>>>(eat_s, eat_d, eta_s, eta_d, eaa_s, eaa_d);

    for (int l = 0; l < 3; l++) {
        const float *Wa, *ba, *Wt, *bt;
        int IN;
        if (l == 0) {
            Wa = pW1;               ba = pb1;
            Wt = pW1 + INDIM*HID;   bt = pb1 + HID;
            IN = INDIM;
        } else {
            Wa = pW23 + ((l-1)*2 + 0)*HID*HID;  ba = pb23 + ((l-1)*2 + 0)*HID;
            Wt = pW23 + ((l-1)*2 + 1)*HID*HID;  bt = pb23 + ((l-1)*2 + 1)*HID;
            IN = HID;
        }
        const float* As = att_src + (l*3) * HEADS * 8;
        const float* Ad = att_dst + (l*3) * HEADS * 8;
        const float* qp = (l == 0) ? q : q + (l-1)*HID;

        lin_alpha_kernel<<<NB_A + NB_T, 256>>>(l, x_addr, x_tx, Wa, ba, Wt, bt,
                                               As, Ad, qp, IN);
        if (l < 2) {
            agg_kernel<<<NB_T + 2*NB_A, 256>>>(0);        // all 3 relations
        } else {
            agg_kernel<<<2*NB_A, 256>>>(NB_T);            // skip rel0: o_tx unused
        }
        sem_kernel<<<(NADDR + 255)/256, 256>>>(kW + l*HID*HID, kb + l*HID, l & 1);
    }
    final_kernel<<<(NADDR + 255)/256, 256>>>(q + 2*HID, linW, linb, (float*)d_out);
}